// round 7
// baseline (speedup 1.0000x reference)
#include <cuda_runtime.h>
#include <math.h>
#include <stdint.h>

#define DIM   512
#define NS    8
#define BATCH 128
#define NTOK  1024
#define HIDN  512
#define NROWS (BATCH*NTOK)   /* 131072 */
#define SROWS (BATCH*NS)     /* 1024   */
#define ATT_SCALE 0.04419417382415922f
#define LN_EPS 1e-5f
#define ATT_EPS 1e-8f

/* ---------------- scratch (device globals; no allocation) ---------------- */
__device__ float g_xn[(size_t)NROWS*DIM];
__device__ float g_kv[(size_t)NROWS*1024];      /* k = cols 0..511, v = cols 512..1023 */
__device__ float g_wkv[1024*DIM];
__device__ float g_bkv[1024];
__device__ float g_Wq_r[DIM*DIM];
__device__ float g_Wih_r[3*DIM*DIM];
__device__ float g_Whh_r[3*DIM*DIM];
__device__ float g_W1_r[HIDN*DIM];
__device__ float g_W2_r[DIM*HIDN];
__device__ float g_s [SROWS*DIM];
__device__ float g_sr[SROWS*DIM];
__device__ float g_q [SROWS*DIM];
__device__ float g_attn[SROWS*NTOK];
__device__ float g_upd[SROWS*DIM];
__device__ float g_xg[SROWS*3*DIM];
__device__ float g_hg[SROWS*3*DIM];
__device__ float g_hid[SROWS*HIDN];

/* ---------------- helpers ---------------- */
__device__ __forceinline__ float rtf32(float x) {
    uint32_t u; asm("cvt.rna.tf32.f32 %0, %1;" : "=r"(u) : "f"(x));
    return __uint_as_float(u);
}
__device__ __forceinline__ uint32_t s2u(const void* p) {
    uint32_t a;
    asm("{ .reg .u64 t; cvta.to.shared.u64 t, %1; cvt.u32.u64 %0, t; }" : "=r"(a) : "l"(p));
    return a;
}
/* pair permutation: new[4j+i] = old[j+4i] within each 16-col block.
   Both GEMM operands stored permuted along K -> dot product unchanged,
   and one LDS.128 yields tf32 fragments (k,k+4,k+8,k+12) for 2 k-steps. */
__host__ __device__ __forceinline__ int kperm(int k) {
    return (k & ~15) | (((k & 3) << 2) | ((k & 15) >> 2));
}

#define CP16(dst, src) \
    asm volatile("cp.async.cg.shared.global [%0], [%1], 16;" :: "r"(dst), "l"(src))
#define CP_COMMIT() asm volatile("cp.async.commit_group;" ::: "memory")
#define CP_WAIT(n)  asm volatile("cp.async.wait_group %0;" :: "n"(n) : "memory")

#define MMA_TF32(d, a0, a1, a2, a3, b0, b1) \
    asm volatile("mma.sync.aligned.m16n8k8.row.col.f32.tf32.tf32.f32 " \
        "{%0,%1,%2,%3}, {%4,%5,%6,%7}, {%8,%9}, {%0,%1,%2,%3};" \
        : "+f"((d)[0]), "+f"((d)[1]), "+f"((d)[2]), "+f"((d)[3]) \
        : "r"(__float_as_uint(a0)), "r"(__float_as_uint(a1)), \
          "r"(__float_as_uint(a2)), "r"(__float_as_uint(a3)), \
          "r"(__float_as_uint(b0)), "r"(__float_as_uint(b1)))

/* ============ tf32 mma.sync GEMM (permuted-K operands) ============
   BM=MT*32, BN=128, BK=32, 256 threads (8 warps, 2m x 4n), 2-stage cp.async,
   ONE __syncthreads per k-iter. ASTR=48 words -> LDS.128 conflict-free. */
#define ASTR 48

template<int MT, int RELU, int ADDC, int RND, int RC, int PERMC>
__device__ __forceinline__ void gemm_body(const float* __restrict__ A,
                                          const float* __restrict__ W,
                                          const float* __restrict__ bias,
                                          float* __restrict__ C,
                                          float* __restrict__ Caux,
                                          int M, int N, int K) {
    extern __shared__ float smem[];
    const int BM = MT * 32;
    const int STGF = (BM + 128) * ASTR;
    int tid = threadIdx.x;
    int lane = tid & 31, wid = tid >> 5;
    int wm = wid & 1, wn = wid >> 1;
    int m0 = blockIdx.y * BM, n0 = blockIdx.x * 128;
    int r0 = lane >> 2, k4 = lane & 3;

    float acc[MT][4][4];
    #pragma unroll
    for (int mt = 0; mt < MT; mt++)
        #pragma unroll
        for (int nt = 0; nt < 4; nt++)
            #pragma unroll
            for (int i = 0; i < 4; i++) acc[mt][nt][i] = 0.f;

    const int KT = K >> 5;

    auto load_stage = [&](int kt, int s) {
        const float* Ag = A + (size_t)m0 * K + (kt << 5);
        const float* Wg = W + (size_t)n0 * K + (kt << 5);
        float* Ab = smem + s * STGF;
        float* Bb = Ab + BM * ASTR;
        #pragma unroll
        for (int i = 0; i < MT; i++) {
            int idx = tid + (i << 8);
            int r = idx >> 3, c4 = (idx & 7) << 2;
            CP16(s2u(Ab + r * ASTR + c4), Ag + (size_t)r * K + c4);
        }
        #pragma unroll
        for (int i = 0; i < 4; i++) {
            int idx = tid + (i << 8);
            int r = idx >> 3, c4 = (idx & 7) << 2;
            CP16(s2u(Bb + r * ASTR + c4), Wg + (size_t)r * K + c4);
        }
    };

    load_stage(0, 0); CP_COMMIT();

    int arow = wm * (MT * 16) + r0;
    int brow = wn * 32 + r0;

    for (int kt = 0; kt < KT; kt++) {
        int s = kt & 1;
        CP_WAIT(0);
        __syncthreads();
        if (kt + 1 < KT) { load_stage(kt + 1, s ^ 1); CP_COMMIT(); }

        const float* Abase = smem + s * STGF;
        const float* Bbase = Abase + BM * ASTR;
        #pragma unroll
        for (int p = 0; p < 2; p++) {
            float4 Bf[4];
            #pragma unroll
            for (int nt = 0; nt < 4; nt++)
                Bf[nt] = *(const float4*)(Bbase + (brow + nt * 8) * ASTR + p * 16 + 4 * k4);
            #pragma unroll
            for (int mt = 0; mt < MT; mt++) {
                float4 A0 = *(const float4*)(Abase + (arow + mt * 16    ) * ASTR + p * 16 + 4 * k4);
                float4 A8 = *(const float4*)(Abase + (arow + mt * 16 + 8) * ASTR + p * 16 + 4 * k4);
                #pragma unroll
                for (int nt = 0; nt < 4; nt++) {
                    MMA_TF32(acc[mt][nt], A0.x, A8.x, A0.y, A8.y, Bf[nt].x, Bf[nt].y);
                    MMA_TF32(acc[mt][nt], A0.z, A8.z, A0.w, A8.w, Bf[nt].z, Bf[nt].w);
                }
            }
        }
    }

    /* epilogue */
    #pragma unroll
    for (int mt = 0; mt < MT; mt++) {
        int mg = m0 + wm * (MT * 16) + mt * 16 + r0;
        #pragma unroll
        for (int nt = 0; nt < 4; nt++) {
            int ng = n0 + wn * 32 + nt * 8 + (k4 << 1);
            float b0 = bias[ng], b1 = bias[ng + 1];
            float* c0p = C + (size_t)mg * N + ng;
            float* c1p = C + (size_t)(mg + 8) * N + ng;
            float o0 = acc[mt][nt][0] + b0, o1 = acc[mt][nt][1] + b1;
            float o2 = acc[mt][nt][2] + b0, o3 = acc[mt][nt][3] + b1;
            if (RELU) {
                o0 = fmaxf(o0, 0.f); o1 = fmaxf(o1, 0.f);
                o2 = fmaxf(o2, 0.f); o3 = fmaxf(o3, 0.f);
            }
            if (ADDC) {
                float2 e0 = *(const float2*)c0p;
                float2 e1 = *(const float2*)c1p;
                o0 += e0.x; o1 += e0.y; o2 += e1.x; o3 += e1.y;
            }
            if (RND) { o0 = rtf32(o0); o1 = rtf32(o1); o2 = rtf32(o2); o3 = rtf32(o3); }
            if (PERMC) {
                int p0 = kperm(ng), p1 = kperm(ng + 1);
                C[(size_t)mg * N + p0] = o0; C[(size_t)mg * N + p1] = o1;
                C[(size_t)(mg + 8) * N + p0] = o2; C[(size_t)(mg + 8) * N + p1] = o3;
            } else {
                *(float2*)c0p = make_float2(o0, o1);
                *(float2*)c1p = make_float2(o2, o3);
            }
            if (RC) {  /* rounded permuted copy for use as next GEMM's A */
                int p0 = kperm(ng), p1 = kperm(ng + 1);
                Caux[(size_t)mg * N + p0] = rtf32(o0);
                Caux[(size_t)mg * N + p1] = rtf32(o1);
                Caux[(size_t)(mg + 8) * N + p0] = rtf32(o2);
                Caux[(size_t)(mg + 8) * N + p1] = rtf32(o3);
            }
        }
    }
}

template<int MT, int RELU, int ADDC, int RND, int RC, int PERMC>
__global__ __launch_bounds__(256, 2) void mma_gemm(const float* __restrict__ A,
                                                   const float* __restrict__ W,
                                                   const float* __restrict__ bias,
                                                   float* __restrict__ C,
                                                   float* __restrict__ Caux,
                                                   int M, int N, int K) {
    gemm_body<MT, RELU, ADDC, RND, RC, PERMC>(A, W, bias, C, Caux, M, N, K);
}

/* dual GEMM: blockIdx.z selects operand set (same shape). */
template<int MT>
__global__ __launch_bounds__(256, 2) void mma_gemm_dual(const float* __restrict__ A0,
                                                        const float* __restrict__ W0,
                                                        const float* __restrict__ b0,
                                                        float* __restrict__ C0,
                                                        const float* __restrict__ A1,
                                                        const float* __restrict__ W1,
                                                        const float* __restrict__ b1,
                                                        float* __restrict__ C1,
                                                        int M, int N, int K) {
    if (blockIdx.z == 0) gemm_body<MT, 0, 0, 0, 0, 0>(A0, W0, b0, C0, nullptr, M, N, K);
    else                 gemm_body<MT, 0, 0, 0, 0, 0>(A1, W1, b1, C1, nullptr, M, N, K);
}

#define GSMEM128 ((128 + 128) * ASTR * 4 * 2)   /* 98304 */
#define GSMEM64  ((64 + 128) * ASTR * 4 * 2)    /* 73728 */

/* ------- slot init: slots unpermuted + srd (rounded, K-permuted) ------- */
__global__ void init_slots(const float* __restrict__ noise,
                           const float* __restrict__ mu,
                           const float* __restrict__ logsigma,
                           float* __restrict__ slots,
                           float* __restrict__ srd) {
    int row = blockIdx.x;
    int t = threadIdx.x;            /* 128 */
    int o0 = ((t >> 2) << 4) + (t & 3);
    const float* nr = noise + (size_t)row * DIM;
    float4 out;
    float v[4];
    #pragma unroll
    for (int i = 0; i < 4; i++) {
        int o = o0 + 4 * i;
        v[i] = mu[o] + expf(logsigma[o]) * nr[o];
        slots[(size_t)row * DIM + o] = v[i];
    }
    out.x = rtf32(v[0]); out.y = rtf32(v[1]); out.z = rtf32(v[2]); out.w = rtf32(v[3]);
    *(float4*)(srd + (size_t)row * DIM + 4 * t) = out;
}

/* ---------------- pack+round+permute [Wk;Wv] and biases ---------------- */
__global__ void pack_kv(const float* __restrict__ Wk, const float* __restrict__ bk,
                        const float* __restrict__ Wv, const float* __restrict__ bv,
                        float* __restrict__ Wkv, float* __restrict__ bkv) {
    int i = blockIdx.x * 256 + threadIdx.x;
    float w = (i < DIM * DIM) ? Wk[i] : Wv[i - DIM * DIM];
    Wkv[(i & ~511) + kperm(i & 511)] = rtf32(w);
    if (i < 1024) bkv[i] = (i < 512) ? bk[i] : bv[i - 512];
}

/* ---------------- round+permute copy (weights; K = low 512 stride) ------ */
__global__ void round_copy(const float* __restrict__ src, float* __restrict__ dst, int n) {
    int i = blockIdx.x * 256 + threadIdx.x;
    if (i < n) dst[(i & ~511) + kperm(i & 511)] = rtf32(src[i]);
}

/* ---- row LayerNorm (cols=512), output rounded tf32 + K-permuted ---- */
__global__ void ln_rows(const float* __restrict__ in, float* __restrict__ out,
                        const float* __restrict__ gamma, const float* __restrict__ beta) {
    int row = blockIdx.x;
    int t = threadIdx.x;            /* 128 */
    int o0 = ((t >> 2) << 4) + (t & 3);
    const float* ip = in + (size_t)row * DIM;
    float x[4], g[4], bb[4];
    #pragma unroll
    for (int i = 0; i < 4; i++) {
        int o = o0 + 4 * i;
        x[i] = ip[o]; g[i] = gamma[o]; bb[i] = beta[o];
    }
    float s  = x[0] + x[1] + x[2] + x[3];
    float ss = x[0]*x[0] + x[1]*x[1] + x[2]*x[2] + x[3]*x[3];
    #pragma unroll
    for (int o = 16; o > 0; o >>= 1) {
        s  += __shfl_down_sync(0xffffffffu, s,  o);
        ss += __shfl_down_sync(0xffffffffu, ss, o);
    }
    __shared__ float sh[8];
    int w = t >> 5, l = t & 31;
    if (l == 0) { sh[w] = s; sh[4 + w] = ss; }
    __syncthreads();
    s  = sh[0] + sh[1] + sh[2] + sh[3];
    ss = sh[4] + sh[5] + sh[6] + sh[7];
    float mean = s * (1.0f / DIM);
    float var  = ss * (1.0f / DIM) - mean * mean;
    float rstd = rsqrtf(var + LN_EPS);
    float4 o4;
    o4.x = rtf32((x[0] - mean) * rstd * g[0] + bb[0]);
    o4.y = rtf32((x[1] - mean) * rstd * g[1] + bb[1]);
    o4.z = rtf32((x[2] - mean) * rstd * g[2] + bb[2]);
    o4.w = rtf32((x[3] - mean) * rstd * g[3] + bb[3]);
    *(float4*)(out + (size_t)row * DIM + 4 * t) = o4;
}

/* ---- dots + competitive softmax, smem-staged coalesced K reads. ---- */
#define KSTR 36
__global__ __launch_bounds__(128) void dots_softmax(const float* __restrict__ kv,
                                                    const float* __restrict__ qmat,
                                                    float* __restrict__ attn) {
    int b = blockIdx.y;
    int j0 = blockIdx.x * 128;
    int tid = threadIdx.x;
    __shared__ float qs[NS][DIM];        /* 16 KB */
    __shared__ float kch[128][KSTR];     /* 18 KB */

    {
        const float4* qsrc = (const float4*)(qmat + (size_t)b * NS * DIM);
        for (int idx = tid; idx < NS * DIM / 4; idx += 128) {
            float4 v = qsrc[idx];
            int i = idx >> 7, d4 = idx & 127;
            qs[i][d4*4+0] = v.x; qs[i][d4*4+1] = v.y;
            qs[i][d4*4+2] = v.z; qs[i][d4*4+3] = v.w;
        }
    }

    float acc[NS];
    #pragma unroll
    for (int i = 0; i < NS; i++) acc[i] = 0.f;

    const float* kbase = kv + (size_t)(b * NTOK + j0) * 1024;

    for (int dc = 0; dc < DIM; dc += 32) {
        __syncthreads();
        #pragma unroll
        for (int ii = 0; ii < 8; ii++) {
            int idx = tid + ii * 128;
            int r = idx >> 3, c4 = idx & 7;
            float4 v = *(const float4*)(kbase + (size_t)r * 1024 + dc + c4 * 4);
            *(float4*)&kch[r][c4 * 4] = v;
        }
        __syncthreads();
        #pragma unroll
        for (int c4 = 0; c4 < 8; c4++) {
            float4 k4 = *(const float4*)&kch[tid][c4 * 4];
            #pragma unroll
            for (int i = 0; i < NS; i++) {
                const float* qp = &qs[i][dc + c4 * 4];
                acc[i] += k4.x*qp[0] + k4.y*qp[1] + k4.z*qp[2] + k4.w*qp[3];
            }
        }
    }

    float m = -1e30f;
    #pragma unroll
    for (int i = 0; i < NS; i++) { acc[i] *= ATT_SCALE; m = fmaxf(m, acc[i]); }
    float sum = 0.f;
    #pragma unroll
    for (int i = 0; i < NS; i++) { acc[i] = expf(acc[i] - m); sum += acc[i]; }
    float inv = 1.0f / sum;
    int j = j0 + tid;
    #pragma unroll
    for (int i = 0; i < NS; i++)
        attn[(size_t)(b * NS + i) * NTOK + j] = acc[i] * inv + ATT_EPS;
}

/* ---- updates; rowsum fused; output written K-permuted (rounded) ---- */
__global__ __launch_bounds__(128) void attn_apply(const float* __restrict__ kv,
                                                  const float* __restrict__ attn,
                                                  float* __restrict__ upd) {
    int b = blockIdx.y;
    int d = blockIdx.x * 128 + threadIdx.x;
    int t = threadIdx.x;
    __shared__ float as[NS][256];        /* 8 KB */
    __shared__ float rs[NS][4];
    float acc[NS], psum[NS];
    #pragma unroll
    for (int i = 0; i < NS; i++) { acc[i] = 0.f; psum[i] = 0.f; }
    const float* vbase = kv + 512 + d;
    for (int j0 = 0; j0 < NTOK; j0 += 256) {
        __syncthreads();
        #pragma unroll
        for (int s = 0; s < 16; s++) {
            int i = s >> 1;
            int jj = (t + (s << 7)) & 255;
            float a = attn[(size_t)(b * NS + i) * NTOK + j0 + jj];
            as[i][jj] = a;
            psum[i] += a;
        }
        __syncthreads();
        #pragma unroll 8
        for (int jj = 0; jj < 256; jj++) {
            float v = vbase[(size_t)(b * NTOK + j0 + jj) * 1024];
            #pragma unroll
            for (int i = 0; i < NS; i++) acc[i] += v * as[i][jj];
        }
    }
    int w = t >> 5, l = t & 31;
    #pragma unroll
    for (int i = 0; i < NS; i++) {
        float s = psum[i];
        #pragma unroll
        for (int o = 16; o > 0; o >>= 1) s += __shfl_down_sync(0xffffffffu, s, o);
        if (l == 0) rs[i][w] = s;
    }
    __syncthreads();
    int dp = (blockIdx.x * 128) + kperm(t) ;  /* kperm acts within 16-blocks: d=blk*128+t, kperm(d)=blk*128+kperm(t) */
    #pragma unroll
    for (int i = 0; i < NS; i++) {
        float rowsum = rs[i][0] + rs[i][1] + rs[i][2] + rs[i][3];
        upd[(size_t)(b * NS + i) * DIM + dp] = rtf32(acc[i] / rowsum);
    }
}

/* ---------------- GRU gate ---------------- */
__global__ void gru_gate(const float* __restrict__ xg, const float* __restrict__ hg,
                         float* __restrict__ slots) {
    int row = blockIdx.x;
    int c = threadIdx.x;
    size_t base = (size_t)row * 3 * DIM;
    float xr = xg[base + c],         hr = hg[base + c];
    float xz = xg[base + DIM + c],   hz = hg[base + DIM + c];
    float xn = xg[base + 2*DIM + c], hn = hg[base + 2*DIM + c];
    float r = 1.0f / (1.0f + expf(-(xr + hr)));
    float z = 1.0f / (1.0f + expf(-(xz + hz)));
    float n = tanhf(xn + r * hn);
    size_t si = (size_t)row * DIM + c;
    float prev = slots[si];
    slots[si] = (1.0f - z) * n + z * prev;
}

/* ---------------- host ---------------- */
static float* sym(const void* s) {
    void* p = nullptr;
    cudaGetSymbolAddress(&p, s);
    return (float*)p;
}

extern "C" void kernel_launch(void* const* d_in, const int* in_sizes, int n_in,
                              void* d_out, int out_size) {
    const float* inputs    = (const float*)d_in[0];
    const float* noise     = (const float*)d_in[1];
    const float* mu        = (const float*)d_in[2];
    const float* logsigma  = (const float*)d_in[3];
    const float* gi        = (const float*)d_in[4];
    const float* bei       = (const float*)d_in[5];
    const float* gsl       = (const float*)d_in[6];
    const float* besl      = (const float*)d_in[7];
    const float* gff       = (const float*)d_in[8];
    const float* beff      = (const float*)d_in[9];
    const float* Wq        = (const float*)d_in[10];
    const float* bq        = (const float*)d_in[11];
    const float* Wk        = (const float*)d_in[12];
    const float* bk        = (const float*)d_in[13];
    const float* Wv        = (const float*)d_in[14];
    const float* bv        = (const float*)d_in[15];
    const float* W_ih      = (const float*)d_in[16];
    const float* b_ih      = (const float*)d_in[17];
    const float* W_hh      = (const float*)d_in[18];
    const float* b_hh      = (const float*)d_in[19];
    const float* W1        = (const float*)d_in[20];
    const float* b1        = (const float*)d_in[21];
    const float* W2        = (const float*)d_in[22];
    const float* b2        = (const float*)d_in[23];
    float* slots = (float*)d_out;

    float* xn   = sym(g_xn);
    float* kv   = sym(g_kv);
    float* wkv  = sym(g_wkv);
    float* bkv  = sym(g_bkv);
    float* Wqr  = sym(g_Wq_r);
    float* Wihr = sym(g_Wih_r);
    float* Whhr = sym(g_Whh_r);
    float* W1r  = sym(g_W1_r);
    float* W2r  = sym(g_W2_r);
    float* sbuf = sym(g_s);
    float* srd  = sym(g_sr);
    float* qbuf = sym(g_q);
    float* attn = sym(g_attn);
    float* upd  = sym(g_upd);
    float* xg   = sym(g_xg);
    float* hg   = sym(g_hg);
    float* hid  = sym(g_hid);

    cudaFuncSetAttribute(mma_gemm<4,0,0,0,0,0>, cudaFuncAttributeMaxDynamicSharedMemorySize, GSMEM128);
    cudaFuncSetAttribute(mma_gemm<2,0,0,0,0,0>, cudaFuncAttributeMaxDynamicSharedMemorySize, GSMEM64);
    cudaFuncSetAttribute(mma_gemm<2,1,0,1,0,1>, cudaFuncAttributeMaxDynamicSharedMemorySize, GSMEM64);
    cudaFuncSetAttribute(mma_gemm<2,0,1,0,1,0>, cudaFuncAttributeMaxDynamicSharedMemorySize, GSMEM64);
    cudaFuncSetAttribute(mma_gemm_dual<2>,      cudaFuncAttributeMaxDynamicSharedMemorySize, GSMEM64);

    /* KV gemm is my launch #4 (ncu -s 5 -c 1 captures it) */
    init_slots<<<SROWS, 128>>>(noise, mu, logsigma, slots, srd);              /* 1 */
    pack_kv<<<1024*DIM/256, 256>>>(Wk, bk, Wv, bv, wkv, bkv);                 /* 2 */
    ln_rows<<<NROWS, 128>>>(inputs, xn, gi, bei);                             /* 3 */
    mma_gemm<4,0,0,0,0,0><<<dim3(1024/128, NROWS/128), 256, GSMEM128>>>(      /* 4 */
        xn, wkv, bkv, kv, nullptr, NROWS, 1024, DIM);
    round_copy<<<DIM*DIM/256, 256>>>(Wq, Wqr, DIM*DIM);
    round_copy<<<3*DIM*DIM/256, 256>>>(W_ih, Wihr, 3*DIM*DIM);
    round_copy<<<3*DIM*DIM/256, 256>>>(W_hh, Whhr, 3*DIM*DIM);
    round_copy<<<HIDN*DIM/256, 256>>>(W1, W1r, HIDN*DIM);
    round_copy<<<DIM*HIDN/256, 256>>>(W2, W2r, DIM*HIDN);

    for (int it = 0; it < 3; it++) {
        ln_rows<<<SROWS, 128>>>(slots, sbuf, gsl, besl);
        mma_gemm<2,0,0,0,0,0><<<dim3(DIM/128, SROWS/64), 256, GSMEM64>>>(sbuf, Wqr, bq, qbuf, nullptr, SROWS, DIM, DIM);
        dots_softmax<<<dim3(NTOK/128, BATCH), 128>>>(kv, qbuf, attn);
        attn_apply<<<dim3(DIM/128, BATCH), 128>>>(kv, attn, upd);
        mma_gemm_dual<2><<<dim3(3*DIM/128, SROWS/64, 2), 256, GSMEM64>>>(
            upd, Wihr, b_ih, xg, srd, Whhr, b_hh, hg, SROWS, 3*DIM, DIM);
        gru_gate<<<SROWS, DIM>>>(xg, hg, slots);
        ln_rows<<<SROWS, 128>>>(slots, sbuf, gff, beff);
        mma_gemm<2,1,0,1,0,1><<<dim3(HIDN/128, SROWS/64), 256, GSMEM64>>>(sbuf, W1r, b1, hid, nullptr, SROWS, HIDN, DIM);
        mma_gemm<2,0,1,0,1,0><<<dim3(DIM/128, SROWS/64), 256, GSMEM64>>>(hid, W2r, b2, slots, srd, SROWS, DIM, HIDN);
    }
    (void)in_sizes; (void)n_in; (void)out_size;
}